// round 1
// baseline (speedup 1.0000x reference)
#include <cuda_runtime.h>
#include <climits>
#include <cstring>
#include <cstdint>

#define HH 6144
#define WW 6144
#define G  50

#define TPB    128
#define SLAB   128
#define STRIPW 512   // TPB * 4 columns

// -------- device scratch (no allocs allowed) --------
__device__ int    g_vys[WW * G];      // sorted vertical thresholds per column (H-1 -> INT_MAX)
__device__ int    g_hcross[WW * G];   // sorted horizontal crossing rows per column, INT_MAX padded
__device__ int    g_hbase[WW];        // horizontal count at y_eff = 1
__device__ double g_binh[G];
__device__ double g_binv[G];

// ---------------- setup: build per-column threshold tables ----------------
__global__ void setup_kernel(const float* rho_max_p, const float* rho_min_p,
                             const float* thmin_p,  const float* thmax_p,
                             const float* tvmin_p,  const float* tvmax_p) {
    __shared__ float Th[G], Ch[G], Av[G], Bv[G];
    int tid = threadIdx.x;
    float rho_max = *rho_max_p, rho_min = *rho_min_p;
    float thmin = *thmin_p, thmax = *thmax_p;
    float tvmin = *tvmin_p, tvmax = *tvmax_p;
    if (tid < G) {
        float t   = (float)tid / 49.0f;
        float thg = __fadd_rn(thmin,   __fmul_rn(__fadd_rn(thmax, -thmin), t));
        float tvg = __fadd_rn(tvmin,   __fmul_rn(__fadd_rn(tvmax, -tvmin), t));
        float rg  = __fadd_rn(rho_max, __fmul_rn(__fadd_rn(rho_min, -rho_max), t));
        Th[tid] = tanf(thg);
        Ch[tid] = rg / cosf(thg);
        Av[tid] = tanf(tvg);
        Bv[tid] = rg / sinf(tvg);
    }
    if (blockIdx.x == 0 && tid < G) { g_binh[tid] = 0.0; g_binv[tid] = 0.0; }
    __syncthreads();

    int x = blockIdx.x * blockDim.x + tid;
    if (x >= WW) return;
    int xe = x; if (xe < 1) xe = 1; if (xe > WW - 2) xe = WW - 2;
    float xef = (float)xe;

    // ---- vertical thresholds: y_g(xe) = round(-xe/tan(tv) + rho/sin(tv)), clip [0,H-1]
    int vv[G];
    float nx = -(float)xe;
    for (int g = 0; g < G; ++g) {
        float val = __fadd_rn(__fdiv_rn(nx, Av[g]), Bv[g]);
        int iv = (int)rintf(val);
        if (iv < 0) iv = 0;
        if (iv >= HH - 1) iv = INT_MAX;   // y_eff <= H-2 never reaches H-1
        vv[g] = iv;
    }
    for (int i = 1; i < G; ++i) {        // insertion sort ascending (near-sorted input)
        int key = vv[i]; int j = i - 1;
        while (j >= 0 && vv[j] > key) { vv[j + 1] = vv[j]; --j; }
        vv[j + 1] = key;
    }
    for (int g = 0; g < G; ++g) g_vys[x * G + g] = vv[g];

    // ---- horizontal: P(y) := round(-y*tan + rho/cos) <= xe, monotone false->true in y
    int base = 0, nc = 0;
    int cr[G];
    for (int g = 0; g < G; ++g) {
        float T = Th[g], C = Ch[g];
        float v1 = rintf(__fadd_rn(__fmul_rn(-1.0f, T), C));
        if (v1 <= xef) { base++; continue; }                 // true from the start
        float vH = rintf(__fadd_rn(__fmul_rn(-(float)(HH - 2), T), C));
        if (!(vH <= xef)) continue;                          // never true in range
        int lo = 1, hi = HH - 2;                             // P(lo)=F, P(hi)=T
        while (hi - lo > 1) {
            int mid = (lo + hi) >> 1;
            float vm = rintf(__fadd_rn(__fmul_rn(-(float)mid, T), C));
            if (vm <= xef) hi = mid; else lo = mid;
        }
        cr[nc++] = hi;
    }
    for (int i = 1; i < nc; ++i) {
        int key = cr[i]; int j = i - 1;
        while (j >= 0 && cr[j] > key) { cr[j + 1] = cr[j]; --j; }
        cr[j + 1] = key;
    }
    for (int i = nc; i < G; ++i) cr[i] = INT_MAX;
    for (int g = 0; g < G; ++g) g_hcross[x * G + g] = cr[g];
    g_hbase[x] = base;
}

// ---------------- main pass: monotone event walkers, 4 columns / thread ----------------
__global__ void __launch_bounds__(TPB) main_kernel(const float* __restrict__ sp) {
    __shared__ float sh[G], sv[G];
    int tid = threadIdx.x;
    if (tid < G) { sh[tid] = 0.f; sv[tid] = 0.f; }
    __syncthreads();

    int c0 = blockIdx.x * STRIPW + tid * 4;
    int y0 = blockIdx.y * SLAB;
    int y1 = y0 + SLAB;
    int y0e = (y0 < 1) ? 1 : y0;

    int vidx[4], vnxt[4], hidx[4], hptr[4], hnxt[4], xs[4];
    for (int c = 0; c < 4; ++c) {
        int x = c0 + c; xs[c] = x;
        const int* vt = &g_vys[x * G];
        int lo = 0, hi = G;
        while (lo < hi) { int m = (lo + hi) >> 1; if (vt[m] <= y0e) lo = m + 1; else hi = m; }
        vidx[c] = lo;
        vnxt[c] = (lo < G) ? vt[lo] : INT_MAX;

        const int* ht = &g_hcross[x * G];
        lo = 0; hi = G;
        while (lo < hi) { int m = (lo + hi) >> 1; if (ht[m] <= y0e) lo = m + 1; else hi = m; }
        hptr[c] = lo;
        hidx[c] = g_hbase[x] + lo;
        hnxt[c] = (lo < G) ? ht[lo] : INT_MAX;
    }

    unsigned long long acc01 = 0ull, acc23 = 0ull;   // packed f32x2 accumulators
    const ulonglong2* p = reinterpret_cast<const ulonglong2*>(sp + (size_t)y0 * WW + c0);
    const int rowstride = WW / 4;                    // ulonglong2 per row

    int y = y0;
    while (y < y1) {
        int nxtmin = min(min(min(vnxt[0], vnxt[1]), min(vnxt[2], vnxt[3])),
                         min(min(hnxt[0], hnxt[1]), min(hnxt[2], hnxt[3])));
        int stop = min(y1, nxtmin);
        #pragma unroll 4
        for (; y < stop; ++y) {
            ulonglong2 u = *p;
            asm("add.rn.f32x2 %0, %0, %1;" : "+l"(acc01) : "l"(u.x));
            asm("add.rn.f32x2 %0, %0, %1;" : "+l"(acc23) : "l"(u.y));
            p += rowstride;
        }
        if (y >= y1) break;

        // ---- event at row y (rare): flush affected columns, advance walkers
        float2 f01, f23;
        memcpy(&f01, &acc01, 8); memcpy(&f23, &acc23, 8);
        float a[4] = { f01.x, f01.y, f23.x, f23.y };
        for (int c = 0; c < 4; ++c) {
            if (hnxt[c] <= y || vnxt[c] <= y) {
                if (hidx[c] < G) atomicAdd(&sh[hidx[c]], a[c]);
                if (vidx[c] < G) atomicAdd(&sv[vidx[c]], a[c]);
                a[c] = 0.f;
                const int* ht = &g_hcross[xs[c] * G];
                while (hnxt[c] <= y) {
                    hidx[c]++; hptr[c]++;
                    hnxt[c] = (hptr[c] < G) ? ht[hptr[c]] : INT_MAX;
                }
                const int* vt = &g_vys[xs[c] * G];
                while (vnxt[c] <= y) {
                    vidx[c]++;
                    vnxt[c] = (vidx[c] < G) ? vt[vidx[c]] : INT_MAX;
                }
            }
        }
        float2 n01 = make_float2(a[0], a[1]);
        float2 n23 = make_float2(a[2], a[3]);
        memcpy(&acc01, &n01, 8); memcpy(&acc23, &n23, 8);
    }

    // residual flush
    {
        float2 f01, f23;
        memcpy(&f01, &acc01, 8); memcpy(&f23, &acc23, 8);
        float a[4] = { f01.x, f01.y, f23.x, f23.y };
        for (int c = 0; c < 4; ++c) {
            if (hidx[c] < G) atomicAdd(&sh[hidx[c]], a[c]);
            if (vidx[c] < G) atomicAdd(&sv[vidx[c]], a[c]);
        }
    }
    __syncthreads();
    if (tid < G) {
        atomicAdd(&g_binh[tid], (double)sh[tid]);
        atomicAdd(&g_binv[tid], (double)sv[tid]);
    }
}

// ---------------- final: percentiles + intersections ----------------
__device__ __forceinline__ float lin_f(float a, float b, int i) {
    float t = (float)i / 49.0f;
    return __fadd_rn(a, __fmul_rn(__fadd_rn(b, -a), t));
}

__global__ void final_kernel(float* out,
                             const float* rho_max_p, const float* rho_min_p,
                             const float* thmin_p,  const float* thmax_p,
                             const float* tvmin_p,  const float* tvmax_p) {
    if (threadIdx.x != 0 || blockIdx.x != 0) return;

    double cumh[G], cumv[G];
    double th_tot = 0, tv_tot = 0;
    for (int s = 0; s < G; ++s) { th_tot += g_binh[s]; tv_tot += g_binv[s]; }
    {
        double c = 0;
        for (int s = 0; s < G; ++s) { c += g_binh[s]; cumh[s] = c / th_tot; }
        c = 0;
        for (int s = 0; s < G; ++s) { c += g_binv[s]; cumv[s] = c / tv_tot; }
    }
    int lower_h = 0, upper_h, lower_v = 0, upper_v;
    for (int s = 0; s < G; ++s) { if (cumh[s] >= 0.01) { lower_h = s; break; } }
    {
        int j = 0;
        for (int jj = 0; jj < G; ++jj) { if (cumh[G - 1 - jj] <= 0.99) { j = jj; break; } }
        upper_h = (G - 1) - j + 2;
    }
    for (int s = 0; s < G; ++s) { if (cumv[s] >= 0.01) { lower_v = s; break; } }
    {
        int j = 0;
        for (int jj = 0; jj < G; ++jj) { if (cumv[G - 1 - jj] <= 0.99) { j = jj; break; } }
        upper_v = (G - 1) - j + 2;
    }

    float rho_max = *rho_max_p, rho_min = *rho_min_p;
    float thmin = *thmin_p, thmax = *thmax_p;
    float tvmin = *tvmin_p, tvmax = *tvmax_p;

    int i_lh = ((G - lower_h) % G + G) % G;
    int i_uh = ((G - upper_h) % G + G) % G;
    int i_lv = ((G - lower_v) % G + G) % G;
    int i_uv = ((G - upper_v) % G + G) % G;

    float r_min_h = lin_f(rho_max, rho_min, i_lh), t_min_h = lin_f(thmin, thmax, i_lh);
    float r_max_h = lin_f(rho_max, rho_min, i_uh), t_max_h = lin_f(thmin, thmax, i_uh);
    float r_min_v = lin_f(rho_max, rho_min, i_lv), t_min_v = lin_f(tvmin, tvmax, i_lv);
    float r_max_v = lin_f(rho_max, rho_min, i_uv), t_max_v = lin_f(tvmin, tvmax, i_uv);

    // intersections (fp32, as reference)
    float r1, t1, r2, t2;
    #define ISECT(o)                                                        \
        {                                                                   \
            float det = cosf(t1) * sinf(t2) - cosf(t2) * sinf(t1);          \
            out[(o) * 2 + 0] = (r1 * sinf(t2) - r2 * sinf(t1)) / det;       \
            out[(o) * 2 + 1] = (r2 * cosf(t1) - r1 * cosf(t2)) / det;       \
        }
    r1 = r_min_h; t1 = t_min_h; r2 = r_min_v; t2 = t_min_v; ISECT(0)  // top-left
    r1 = r_max_h; t1 = t_max_h; r2 = r_min_v; t2 = t_min_v; ISECT(1)  // top-right
    r1 = r_max_h; t1 = t_max_h; r2 = r_max_v; t2 = t_max_v; ISECT(2)  // bottom-right
    r1 = r_min_h; t1 = t_min_h; r2 = r_max_v; t2 = t_max_v; ISECT(3)  // bottom-left
    #undef ISECT
}

// ---------------- launch ----------------
extern "C" void kernel_launch(void* const* d_in, const int* in_sizes, int n_in,
                              void* d_out, int out_size) {
    const float* sp    = (const float*)d_in[0];
    const float* rmax  = (const float*)d_in[1];
    const float* rmin  = (const float*)d_in[2];
    const float* thmin = (const float*)d_in[3];
    const float* thmax = (const float*)d_in[4];
    const float* tvmin = (const float*)d_in[5];
    const float* tvmax = (const float*)d_in[6];

    setup_kernel<<<WW / 256, 256>>>(rmax, rmin, thmin, thmax, tvmin, tvmax);
    dim3 grid(WW / STRIPW, HH / SLAB);
    main_kernel<<<grid, TPB>>>(sp);
    final_kernel<<<1, 32>>>((float*)d_out, rmax, rmin, thmin, thmax, tvmin, tvmax);
}

// round 2
// speedup vs baseline: 1.5404x; 1.5404x over previous
#include <cuda_runtime.h>
#include <climits>
#include <cstring>
#include <cstdint>

#define HH 6144
#define WW 6144
#define G  50

#define TPB    128
#define SLAB   128
#define STRIPW 512   // TPB * 4 columns
#define BATCH  8

// -------- device scratch (no allocs allowed) --------
__device__ int    g_vys[WW * G];      // sorted vertical thresholds per column (>=H-1 -> INT_MAX)
__device__ int    g_hcross[WW * G];   // sorted horizontal crossing rows per column (base lines -> 1), INT_MAX padded
__device__ double g_binh[G];
__device__ double g_binv[G];

// ---------------- setup: one thread per (x,g); rank-sort via shared ----------------
__global__ void setup_kernel(const float* rho_max_p, const float* rho_min_p,
                             const float* thmin_p,  const float* thmax_p,
                             const float* tvmin_p,  const float* tvmax_p) {
    __shared__ float Th[G], Ch[G], Av[G], Bv[G];
    __shared__ int svv[4][64], shh[4][64];

    int g   = threadIdx.x;          // 0..63 (active if < G)
    int ci  = threadIdx.y;          // 0..3  column within block
    int lin = ci * 64 + g;

    if (lin < G) {
        float rho_max = *rho_max_p, rho_min = *rho_min_p;
        float thmin = *thmin_p, thmax = *thmax_p;
        float tvmin = *tvmin_p, tvmax = *tvmax_p;
        float t   = (float)lin / 49.0f;
        float thg = __fadd_rn(thmin,   __fmul_rn(__fadd_rn(thmax, -thmin), t));
        float tvg = __fadd_rn(tvmin,   __fmul_rn(__fadd_rn(tvmax, -tvmin), t));
        float rg  = __fadd_rn(rho_max, __fmul_rn(__fadd_rn(rho_min, -rho_max), t));
        Th[lin] = tanf(thg);
        Ch[lin] = rg / cosf(thg);
        Av[lin] = tanf(tvg);
        Bv[lin] = rg / sinf(tvg);
        if (blockIdx.x == 0) { g_binh[lin] = 0.0; g_binv[lin] = 0.0; }
    }
    __syncthreads();

    int x  = blockIdx.x * 4 + ci;
    int xe = x; if (xe < 1) xe = 1; if (xe > WW - 2) xe = WW - 2;
    float xef = (float)xe;

    int vval = INT_MAX, hval = INT_MAX;
    if (g < G) {
        // vertical threshold: y_g(xe) = round(-xe/tan(tv) + rho/sin(tv)), clip >= 0;
        // thresholds >= H-1 never trigger (y_eff <= H-2)
        float val = __fadd_rn(__fdiv_rn(-(float)xe, Av[g]), Bv[g]);
        int iv = (int)rintf(val);
        if (iv < 0) iv = 0;
        vval = (iv >= HH - 1) ? INT_MAX : iv;

        // horizontal: P(y) := round(-y*T + C) <= xe, monotone false->true in y over [1, H-2]
        float T = Th[g], C = Ch[g];
        float v1 = rintf(__fadd_rn(-T, C));
        if (v1 <= xef) {
            hval = 1;  // "base" line: true from the start -> crossing at row 1
        } else {
            float vH = rintf(__fadd_rn(__fmul_rn(-(float)(HH - 2), T), C));
            if (vH <= xef) {
                int lo = 1, hi = HH - 2;                  // P(lo)=F, P(hi)=T
                while (hi - lo > 1) {
                    int mid = (lo + hi) >> 1;
                    float vm = rintf(__fadd_rn(__fmul_rn(-(float)mid, T), C));
                    if (vm <= xef) hi = mid; else lo = mid;
                }
                hval = hi;
            }
        }
    }
    svv[ci][g] = vval;
    shh[ci][g] = hval;
    __syncthreads();

    if (g < G) {
        int rv = 0, rh = 0;
        #pragma unroll 10
        for (int j = 0; j < G; ++j) {
            int w = svv[ci][j];
            rv += (w < vval) || (w == vval && j < g);
            int h = shh[ci][j];
            rh += (h < hval) || (h == hval && j < g);
        }
        g_vys[x * G + rv]    = vval;
        g_hcross[x * G + rh] = hval;
    }
}

// ---------------- main pass: monotone event walkers, 4 columns / thread ----------------
__global__ void __launch_bounds__(TPB, 4) main_kernel(const float* __restrict__ sp) {
    __shared__ float sh[G], sv[G];
    int tid = threadIdx.x;
    if (tid < G) { sh[tid] = 0.f; sv[tid] = 0.f; }
    __syncthreads();

    int c0 = blockIdx.x * STRIPW + tid * 4;
    int y0 = blockIdx.y * SLAB;
    int y1 = y0 + SLAB;
    int y0e = (y0 < 1) ? 1 : y0;

    int vidx[4], vnxt[4], hidx[4], hnxt[4], xs[4];
    #pragma unroll
    for (int c = 0; c < 4; ++c) {
        int x = c0 + c; xs[c] = x;
        const int* vt = &g_vys[x * G];
        int lo = 0, hi = G;
        while (lo < hi) { int m = (lo + hi) >> 1; if (vt[m] <= y0e) lo = m + 1; else hi = m; }
        vidx[c] = lo;
        vnxt[c] = (lo < G) ? vt[lo] : INT_MAX;

        const int* ht = &g_hcross[x * G];
        lo = 0; hi = G;
        while (lo < hi) { int m = (lo + hi) >> 1; if (ht[m] <= y0e) lo = m + 1; else hi = m; }
        hidx[c] = lo;
        hnxt[c] = (lo < G) ? ht[lo] : INT_MAX;
    }

    unsigned long long acc01 = 0ull, acc23 = 0ull;   // packed f32x2 accumulators
    const ulonglong2* p = reinterpret_cast<const ulonglong2*>(sp + (size_t)y0 * WW + c0);
    const int rowstride = WW / 4;                    // ulonglong2 per row

    int y = y0;
    while (y < y1) {
        int nxtmin = min(min(min(vnxt[0], vnxt[1]), min(vnxt[2], vnxt[3])),
                         min(min(hnxt[0], hnxt[1]), min(hnxt[2], hnxt[3])));
        int stop = min(y1, nxtmin);

        // batched event-free span: BATCH independent LDG.128 in flight
        while (y + BATCH <= stop) {
            ulonglong2 u[BATCH];
            #pragma unroll
            for (int i = 0; i < BATCH; ++i) u[i] = p[i * rowstride];
            #pragma unroll
            for (int i = 0; i < BATCH; ++i) {
                asm("add.rn.f32x2 %0, %0, %1;" : "+l"(acc01) : "l"(u[i].x));
                asm("add.rn.f32x2 %0, %0, %1;" : "+l"(acc23) : "l"(u[i].y));
            }
            p += BATCH * rowstride;
            y += BATCH;
        }
        for (; y < stop; ++y) {
            ulonglong2 u = *p;
            asm("add.rn.f32x2 %0, %0, %1;" : "+l"(acc01) : "l"(u.x));
            asm("add.rn.f32x2 %0, %0, %1;" : "+l"(acc23) : "l"(u.y));
            p += rowstride;
        }
        if (y >= y1) break;

        // ---- event at row y (rare): flush affected columns, advance walkers
        float2 f01, f23;
        memcpy(&f01, &acc01, 8); memcpy(&f23, &acc23, 8);
        float a[4] = { f01.x, f01.y, f23.x, f23.y };
        #pragma unroll
        for (int c = 0; c < 4; ++c) {
            if (hnxt[c] <= y || vnxt[c] <= y) {
                if (hidx[c] < G) atomicAdd(&sh[hidx[c]], a[c]);
                if (vidx[c] < G) atomicAdd(&sv[vidx[c]], a[c]);
                a[c] = 0.f;
                const int* ht = &g_hcross[xs[c] * G];
                while (hnxt[c] <= y) {
                    hidx[c]++;
                    hnxt[c] = (hidx[c] < G) ? ht[hidx[c]] : INT_MAX;
                }
                const int* vt = &g_vys[xs[c] * G];
                while (vnxt[c] <= y) {
                    vidx[c]++;
                    vnxt[c] = (vidx[c] < G) ? vt[vidx[c]] : INT_MAX;
                }
            }
        }
        float2 n01 = make_float2(a[0], a[1]);
        float2 n23 = make_float2(a[2], a[3]);
        memcpy(&acc01, &n01, 8); memcpy(&acc23, &n23, 8);
    }

    // residual flush
    {
        float2 f01, f23;
        memcpy(&f01, &acc01, 8); memcpy(&f23, &acc23, 8);
        float a[4] = { f01.x, f01.y, f23.x, f23.y };
        #pragma unroll
        for (int c = 0; c < 4; ++c) {
            if (hidx[c] < G) atomicAdd(&sh[hidx[c]], a[c]);
            if (vidx[c] < G) atomicAdd(&sv[vidx[c]], a[c]);
        }
    }
    __syncthreads();
    if (tid < G) {
        atomicAdd(&g_binh[tid], (double)sh[tid]);
        atomicAdd(&g_binv[tid], (double)sv[tid]);
    }
}

// ---------------- final: percentiles + intersections ----------------
__device__ __forceinline__ float lin_f(float a, float b, int i) {
    float t = (float)i / 49.0f;
    return __fadd_rn(a, __fmul_rn(__fadd_rn(b, -a), t));
}

__global__ void final_kernel(float* out,
                             const float* rho_max_p, const float* rho_min_p,
                             const float* thmin_p,  const float* thmax_p,
                             const float* tvmin_p,  const float* tvmax_p) {
    if (threadIdx.x != 0 || blockIdx.x != 0) return;

    double cumh[G], cumv[G];
    double th_tot = 0, tv_tot = 0;
    for (int s = 0; s < G; ++s) { th_tot += g_binh[s]; tv_tot += g_binv[s]; }
    {
        double c = 0;
        for (int s = 0; s < G; ++s) { c += g_binh[s]; cumh[s] = c / th_tot; }
        c = 0;
        for (int s = 0; s < G; ++s) { c += g_binv[s]; cumv[s] = c / tv_tot; }
    }
    int lower_h = 0, upper_h, lower_v = 0, upper_v;
    for (int s = 0; s < G; ++s) { if (cumh[s] >= 0.01) { lower_h = s; break; } }
    {
        int j = 0;
        for (int jj = 0; jj < G; ++jj) { if (cumh[G - 1 - jj] <= 0.99) { j = jj; break; } }
        upper_h = (G - 1) - j + 2;
    }
    for (int s = 0; s < G; ++s) { if (cumv[s] >= 0.01) { lower_v = s; break; } }
    {
        int j = 0;
        for (int jj = 0; jj < G; ++jj) { if (cumv[G - 1 - jj] <= 0.99) { j = jj; break; } }
        upper_v = (G - 1) - j + 2;
    }

    float rho_max = *rho_max_p, rho_min = *rho_min_p;
    float thmin = *thmin_p, thmax = *thmax_p;
    float tvmin = *tvmin_p, tvmax = *tvmax_p;

    int i_lh = ((G - lower_h) % G + G) % G;
    int i_uh = ((G - upper_h) % G + G) % G;
    int i_lv = ((G - lower_v) % G + G) % G;
    int i_uv = ((G - upper_v) % G + G) % G;

    float r_min_h = lin_f(rho_max, rho_min, i_lh), t_min_h = lin_f(thmin, thmax, i_lh);
    float r_max_h = lin_f(rho_max, rho_min, i_uh), t_max_h = lin_f(thmin, thmax, i_uh);
    float r_min_v = lin_f(rho_max, rho_min, i_lv), t_min_v = lin_f(tvmin, tvmax, i_lv);
    float r_max_v = lin_f(rho_max, rho_min, i_uv), t_max_v = lin_f(tvmin, tvmax, i_uv);

    float r1, t1, r2, t2;
    #define ISECT(o)                                                        \
        {                                                                   \
            float det = cosf(t1) * sinf(t2) - cosf(t2) * sinf(t1);          \
            out[(o) * 2 + 0] = (r1 * sinf(t2) - r2 * sinf(t1)) / det;       \
            out[(o) * 2 + 1] = (r2 * cosf(t1) - r1 * cosf(t2)) / det;       \
        }
    r1 = r_min_h; t1 = t_min_h; r2 = r_min_v; t2 = t_min_v; ISECT(0)  // top-left
    r1 = r_max_h; t1 = t_max_h; r2 = r_min_v; t2 = t_min_v; ISECT(1)  // top-right
    r1 = r_max_h; t1 = t_max_h; r2 = r_max_v; t2 = t_max_v; ISECT(2)  // bottom-right
    r1 = r_min_h; t1 = t_min_h; r2 = r_max_v; t2 = t_max_v; ISECT(3)  // bottom-left
    #undef ISECT
}

// ---------------- launch ----------------
extern "C" void kernel_launch(void* const* d_in, const int* in_sizes, int n_in,
                              void* d_out, int out_size) {
    const float* sp    = (const float*)d_in[0];
    const float* rmax  = (const float*)d_in[1];
    const float* rmin  = (const float*)d_in[2];
    const float* thmin = (const float*)d_in[3];
    const float* thmax = (const float*)d_in[4];
    const float* tvmin = (const float*)d_in[5];
    const float* tvmax = (const float*)d_in[6];

    dim3 sblk(64, 4);
    setup_kernel<<<WW / 4, sblk>>>(rmax, rmin, thmin, thmax, tvmin, tvmax);
    dim3 grid(WW / STRIPW, HH / SLAB);
    main_kernel<<<grid, TPB>>>(sp);
    final_kernel<<<1, 32>>>((float*)d_out, rmax, rmin, thmin, thmax, tvmin, tvmax);
}

// round 3
// speedup vs baseline: 2.2917x; 1.4877x over previous
#include <cuda_runtime.h>
#include <climits>
#include <cstring>
#include <cstdint>

#define HH 6144
#define WW 6144
#define G  50

#define TPB    128
#define SLAB   128
#define STRIPW 512   // TPB * 4 columns
#define BATCH  8

// -------- device scratch (no allocs allowed) --------
__device__ int    g_vys[WW * G];      // sorted vertical thresholds per column (>=H-1 -> INT_MAX)
__device__ int    g_hcross[WW * G];   // sorted horizontal crossing rows per column (base -> 1), INT_MAX padded
__device__ double g_binh[G];
__device__ double g_binv[G];

// ---------------- setup: one thread per (x,g); estimate+fixup; rank-sort via shared ----------------
__global__ void setup_kernel(const float* rho_max_p, const float* rho_min_p,
                             const float* thmin_p,  const float* thmax_p,
                             const float* tvmin_p,  const float* tvmax_p) {
    __shared__ float Th[G], Ch[G], Av[G], Bv[G];
    __shared__ int svv[4][64], shh[4][64];

    int g   = threadIdx.x;          // 0..63 (active if < G)
    int ci  = threadIdx.y;          // 0..3  column within block
    int lin = ci * 64 + g;

    if (lin < G) {
        float rho_max = *rho_max_p, rho_min = *rho_min_p;
        float thmin = *thmin_p, thmax = *thmax_p;
        float tvmin = *tvmin_p, tvmax = *tvmax_p;
        float t   = (float)lin / 49.0f;
        float thg = __fadd_rn(thmin,   __fmul_rn(__fadd_rn(thmax, -thmin), t));
        float tvg = __fadd_rn(tvmin,   __fmul_rn(__fadd_rn(tvmax, -tvmin), t));
        float rg  = __fadd_rn(rho_max, __fmul_rn(__fadd_rn(rho_min, -rho_max), t));
        Th[lin] = tanf(thg);
        Ch[lin] = rg / cosf(thg);
        Av[lin] = tanf(tvg);
        Bv[lin] = rg / sinf(tvg);
        if (blockIdx.x == 0) { g_binh[lin] = 0.0; g_binv[lin] = 0.0; }
    }
    __syncthreads();

    int x  = blockIdx.x * 4 + ci;
    int xe = x; if (xe < 1) xe = 1; if (xe > WW - 2) xe = WW - 2;
    float xef = (float)xe;

    int vval = INT_MAX, hval = INT_MAX;
    if (g < G) {
        // vertical threshold: y_g(xe) = round(-xe/tan(tv) + rho/sin(tv)), clip >= 0;
        // thresholds >= H-1 never trigger (y_eff <= H-2)
        float val = __fadd_rn(__fdiv_rn(-(float)xe, Av[g]), Bv[g]);
        int iv = (int)rintf(val);
        if (iv < 0) iv = 0;
        vval = (iv >= HH - 1) ? INT_MAX : iv;

        // horizontal: P(y) := round(-y*T + C) <= xe, monotone false->true in y over [1, H-2]
        float T = Th[g], C = Ch[g];
        float v1 = rintf(__fadd_rn(-T, C));
        if (v1 <= xef) {
            hval = 1;  // "base" line: true from the start -> crossing at row 1
        } else {
            float vH = rintf(__fadd_rn(__fmul_rn(-(float)(HH - 2), T), C));
            if (vH <= xef) {
                // crossing in (1, H-2]: estimate then exact fixup on the fp32 predicate
                double yd = ((double)C - (double)xef - 0.5) / (double)T;
                int yc = (int)ceil(yd);
                if (yc < 2) yc = 2;
                if (yc > HH - 2) yc = HH - 2;
                while (yc > 2 &&
                       rintf(__fadd_rn(__fmul_rn(-(float)(yc - 1), T), C)) <= xef) --yc;
                while (rintf(__fadd_rn(__fmul_rn(-(float)yc, T), C)) > xef) ++yc; // bounded by H-2
                hval = yc;
            }
        }
    }
    svv[ci][g] = vval;
    shh[ci][g] = hval;
    __syncthreads();

    if (g < G) {
        int rv = 0, rh = 0;
        #pragma unroll 10
        for (int j = 0; j < G; ++j) {
            int w = svv[ci][j];
            rv += (w < vval) || (w == vval && j < g);
            int h = shh[ci][j];
            rh += (h < hval) || (h == hval && j < g);
        }
        g_vys[x * G + rv]    = vval;
        g_hcross[x * G + rh] = hval;
    }
}

// ---------------- main pass: unconditional batched loads + event walkers ----------------
__global__ void __launch_bounds__(TPB, 4) main_kernel(const float* __restrict__ sp) {
    __shared__ float sh[G], sv[G];
    int tid = threadIdx.x;
    if (tid < G) { sh[tid] = 0.f; sv[tid] = 0.f; }
    __syncthreads();

    int c0 = blockIdx.x * STRIPW + tid * 4;
    int y0 = blockIdx.y * SLAB;
    int y0e = (y0 < 1) ? 1 : y0;

    int vidx[4], vnxt[4], hidx[4], hnxt[4], xs[4];
    #pragma unroll
    for (int c = 0; c < 4; ++c) {
        int x = c0 + c; xs[c] = x;
        const int* vt = &g_vys[x * G];
        int lo = 0, hi = G;
        while (lo < hi) { int m = (lo + hi) >> 1; if (vt[m] <= y0e) lo = m + 1; else hi = m; }
        vidx[c] = lo;
        vnxt[c] = (lo < G) ? vt[lo] : INT_MAX;

        const int* ht = &g_hcross[x * G];
        lo = 0; hi = G;
        while (lo < hi) { int m = (lo + hi) >> 1; if (ht[m] <= y0e) lo = m + 1; else hi = m; }
        hidx[c] = lo;
        hnxt[c] = (lo < G) ? ht[lo] : INT_MAX;
    }

    int nxtmin = min(min(min(vnxt[0], vnxt[1]), min(vnxt[2], vnxt[3])),
                     min(min(hnxt[0], hnxt[1]), min(hnxt[2], hnxt[3])));

    unsigned long long acc01 = 0ull, acc23 = 0ull;   // packed f32x2 accumulators
    const ulonglong2* p = reinterpret_cast<const ulonglong2*>(sp + (size_t)y0 * WW + c0);
    const int rowstride = WW / 4;                    // ulonglong2 per row

    int y = y0;
    #pragma unroll 1
    for (int b = 0; b < SLAB / BATCH; ++b) {
        // unconditional batch: BATCH independent LDG.128 in flight, every iteration
        ulonglong2 u[BATCH];
        #pragma unroll
        for (int i = 0; i < BATCH; ++i) u[i] = p[i * rowstride];
        p += BATCH * rowstride;

        if (nxtmin >= y + BATCH) {
            // fast path: no events in this batch
            #pragma unroll
            for (int i = 0; i < BATCH; ++i) {
                asm("add.rn.f32x2 %0, %0, %1;" : "+l"(acc01) : "l"(u[i].x));
                asm("add.rn.f32x2 %0, %0, %1;" : "+l"(acc23) : "l"(u[i].y));
            }
        } else {
            // slow path: data already resident; handle events row by row
            #pragma unroll
            for (int i = 0; i < BATCH; ++i) {
                int yy = y + i;
                if (nxtmin <= yy) {
                    float2 f01, f23;
                    memcpy(&f01, &acc01, 8); memcpy(&f23, &acc23, 8);
                    float a[4] = { f01.x, f01.y, f23.x, f23.y };
                    #pragma unroll
                    for (int c = 0; c < 4; ++c) {
                        if (hnxt[c] <= yy || vnxt[c] <= yy) {
                            if (hidx[c] < G) atomicAdd(&sh[hidx[c]], a[c]);
                            if (vidx[c] < G) atomicAdd(&sv[vidx[c]], a[c]);
                            a[c] = 0.f;
                            const int* ht = &g_hcross[xs[c] * G];
                            while (hnxt[c] <= yy) {
                                hidx[c]++;
                                hnxt[c] = (hidx[c] < G) ? ht[hidx[c]] : INT_MAX;
                            }
                            const int* vt = &g_vys[xs[c] * G];
                            while (vnxt[c] <= yy) {
                                vidx[c]++;
                                vnxt[c] = (vidx[c] < G) ? vt[vidx[c]] : INT_MAX;
                            }
                        }
                    }
                    float2 n01 = make_float2(a[0], a[1]);
                    float2 n23 = make_float2(a[2], a[3]);
                    memcpy(&acc01, &n01, 8); memcpy(&acc23, &n23, 8);
                    nxtmin = min(min(min(vnxt[0], vnxt[1]), min(vnxt[2], vnxt[3])),
                                 min(min(hnxt[0], hnxt[1]), min(hnxt[2], hnxt[3])));
                }
                asm("add.rn.f32x2 %0, %0, %1;" : "+l"(acc01) : "l"(u[i].x));
                asm("add.rn.f32x2 %0, %0, %1;" : "+l"(acc23) : "l"(u[i].y));
            }
        }
        y += BATCH;
    }

    // residual flush
    {
        float2 f01, f23;
        memcpy(&f01, &acc01, 8); memcpy(&f23, &acc23, 8);
        float a[4] = { f01.x, f01.y, f23.x, f23.y };
        #pragma unroll
        for (int c = 0; c < 4; ++c) {
            if (hidx[c] < G) atomicAdd(&sh[hidx[c]], a[c]);
            if (vidx[c] < G) atomicAdd(&sv[vidx[c]], a[c]);
        }
    }
    __syncthreads();
    if (tid < G) {
        atomicAdd(&g_binh[tid], (double)sh[tid]);
        atomicAdd(&g_binv[tid], (double)sv[tid]);
    }
}

// ---------------- final: 64-thread scan + percentiles + intersections ----------------
__device__ __forceinline__ float lin_f(float a, float b, int i) {
    float t = (float)i / 49.0f;
    return __fadd_rn(a, __fmul_rn(__fadd_rn(b, -a), t));
}

__global__ void final_kernel(float* out,
                             const float* rho_max_p, const float* rho_min_p,
                             const float* thmin_p,  const float* thmax_p,
                             const float* tvmin_p,  const float* tvmax_p) {
    __shared__ double s_h[64], s_v[64];
    int t = threadIdx.x;  // 64 threads
    s_h[t] = (t < G) ? g_binh[t] : 0.0;
    s_v[t] = (t < G) ? g_binv[t] : 0.0;
    __syncthreads();
    #pragma unroll
    for (int off = 1; off < 64; off <<= 1) {
        double ah = (t >= off) ? s_h[t - off] : 0.0;
        double av = (t >= off) ? s_v[t - off] : 0.0;
        __syncthreads();
        s_h[t] += ah; s_v[t] += av;
        __syncthreads();
    }
    if (t != 0) return;

    double tot_h = s_h[G - 1], tot_v = s_v[G - 1];

    int lower_h = 0, upper_h, lower_v = 0, upper_v;
    for (int s = 0; s < G; ++s) { if (s_h[s] / tot_h >= 0.01) { lower_h = s; break; } }
    {
        int j = 0;
        for (int jj = 0; jj < G; ++jj) { if (s_h[G - 1 - jj] / tot_h <= 0.99) { j = jj; break; } }
        upper_h = (G - 1) - j + 2;
    }
    for (int s = 0; s < G; ++s) { if (s_v[s] / tot_v >= 0.01) { lower_v = s; break; } }
    {
        int j = 0;
        for (int jj = 0; jj < G; ++jj) { if (s_v[G - 1 - jj] / tot_v <= 0.99) { j = jj; break; } }
        upper_v = (G - 1) - j + 2;
    }

    float rho_max = *rho_max_p, rho_min = *rho_min_p;
    float thmin = *thmin_p, thmax = *thmax_p;
    float tvmin = *tvmin_p, tvmax = *tvmax_p;

    int i_lh = ((G - lower_h) % G + G) % G;
    int i_uh = ((G - upper_h) % G + G) % G;
    int i_lv = ((G - lower_v) % G + G) % G;
    int i_uv = ((G - upper_v) % G + G) % G;

    float r_min_h = lin_f(rho_max, rho_min, i_lh), t_min_h = lin_f(thmin, thmax, i_lh);
    float r_max_h = lin_f(rho_max, rho_min, i_uh), t_max_h = lin_f(thmin, thmax, i_uh);
    float r_min_v = lin_f(rho_max, rho_min, i_lv), t_min_v = lin_f(tvmin, tvmax, i_lv);
    float r_max_v = lin_f(rho_max, rho_min, i_uv), t_max_v = lin_f(tvmin, tvmax, i_uv);

    float r1, t1, r2, t2;
    #define ISECT(o)                                                        \
        {                                                                   \
            float det = cosf(t1) * sinf(t2) - cosf(t2) * sinf(t1);          \
            out[(o) * 2 + 0] = (r1 * sinf(t2) - r2 * sinf(t1)) / det;       \
            out[(o) * 2 + 1] = (r2 * cosf(t1) - r1 * cosf(t2)) / det;       \
        }
    r1 = r_min_h; t1 = t_min_h; r2 = r_min_v; t2 = t_min_v; ISECT(0)  // top-left
    r1 = r_max_h; t1 = t_max_h; r2 = r_min_v; t2 = t_min_v; ISECT(1)  // top-right
    r1 = r_max_h; t1 = t_max_h; r2 = r_max_v; t2 = t_max_v; ISECT(2)  // bottom-right
    r1 = r_min_h; t1 = t_min_h; r2 = r_max_v; t2 = t_max_v; ISECT(3)  // bottom-left
    #undef ISECT
}

// ---------------- launch ----------------
extern "C" void kernel_launch(void* const* d_in, const int* in_sizes, int n_in,
                              void* d_out, int out_size) {
    const float* sp    = (const float*)d_in[0];
    const float* rmax  = (const float*)d_in[1];
    const float* rmin  = (const float*)d_in[2];
    const float* thmin = (const float*)d_in[3];
    const float* thmax = (const float*)d_in[4];
    const float* tvmin = (const float*)d_in[5];
    const float* tvmax = (const float*)d_in[6];

    dim3 sblk(64, 4);
    setup_kernel<<<WW / 4, sblk>>>(rmax, rmin, thmin, thmax, tvmin, tvmax);
    dim3 grid(WW / STRIPW, HH / SLAB);
    main_kernel<<<grid, TPB>>>(sp);
    final_kernel<<<1, 64>>>((float*)d_out, rmax, rmin, thmin, thmax, tvmin, tvmax);
}